// round 13
// baseline (speedup 1.0000x reference)
#include <cuda_runtime.h>
#include <cuda_bf16.h>
#include <cstdint>

// -----------------------------------------------------------------------------
// OConnorWeatherall belief update, N=500000, K=64, TRIALS=10.
//
// PASSING arithmetic (R9, bit-exact vs GPU-jax/XLA:GPU — FROZEN):
//   pl   = rn(prior*lik)                      // two uses -> NOT fused (NVPTX)
//   marg = fma(1-prior, alt, pl)              // N1-side fusion
//   cert = max(fma(-(delta*mst), 1-marg, 1), 0)
//   post = fma(bel, cert, rn(mis*(1-cert)))
//   div.rn (__fdiv_rn); pow = libdevice __nv_powf.
//
// R13 = R10 kernel (depth-8 pipeline, guarded fold step — best 143.9us)
//       + __launch_bounds__(256, 6): cap 42 regs -> 6 CTAs/SM.
//   Law from R11/R12: perf ~ CTAs/SM x per-warp MLP; reg-file quantized.
//   Loop spills are cheap (coalesced STL/LDL ~1 wavefront/warp), occupancy
//   +20% attacks the binding L1TEX queue directly.
// -----------------------------------------------------------------------------

extern "C" __device__ float __nv_powf(float, float);   // libdevice (XLA:GPU pow)

#define MAXN 500000
#define BLK  256

__device__ __align__(8) static uint2 g_records[MAXN];

__global__ void pack_kernel(const float* __restrict__ belief,
                            const float2* __restrict__ payoff,
                            int n) {
    int i = blockIdx.x * blockDim.x + threadIdx.x;
    if (i >= n) return;
    float2 st = payoff[i];
    unsigned meta = 0u;
    if (st.y > 0.0f) {
        meta = 0x100u | (unsigned)__float2int_rn(st.x);
    }
    g_records[i] = make_uint2(__float_as_uint(belief[i]), meta);
}

// One fold step: NVPTX hasOneUse-contracted tree (bit-exact, frozen).
// T = thread's private float2 smem column, stride BLK: T[s] = (lik_s, alt_s).
__device__ __forceinline__ float fold_step(float prior, uint2 rec,
                                           const float2* __restrict__ T,
                                           float mst) {
    unsigned meta = rec.y;
    if (meta & 0x100u) {
        float b   = __uint_as_float(rec.x);
        int   s   = (int)(meta & 0xFFu);
        float2 la = T[s * BLK];
        float lik = la.x;
        float alt = la.y;
        float delta = fabsf(__fsub_rn(prior, b));
        float pl    = __fmul_rn(prior, lik);          // 2 uses -> stays a mul
        float marg  = __fmaf_rn(__fsub_rn(1.0f, prior), alt, pl);
        float omm   = __fsub_rn(1.0f, marg);
        float bel   = __fdiv_rn(pl, marg);
        float mis   = __fdiv_rn(__fmul_rn(prior, __fsub_rn(1.0f, lik)), omm);
        float u     = __fmul_rn(delta, mst);
        float cert  = fmaxf(__fmaf_rn(-u, omm, 1.0f), 0.0f);
        prior = __fmaf_rn(bel, cert,
                          __fmul_rn(mis, __fsub_rn(1.0f, cert)));
    }
    return prior;
}

__global__ __launch_bounds__(BLK, 6)
void fold_kernel(const float* __restrict__ belief,
                 const float* __restrict__ prob,
                 const float* __restrict__ mistrust,
                 const int*   __restrict__ nbr,
                 float*       __restrict__ out,
                 int n) {
    __shared__ float2 Tsh[11 * BLK];
    int tid = threadIdx.x;
    int i = blockIdx.x * BLK + tid;
    bool valid = (i < n);

    float p = valid ? prob[i] : 0.7f;
    float q = __fsub_rn(1.0f, p);

    // lik[s] = rn( __nv_powf(p,s) * __nv_powf(q,10-s) ); alt[s] = lik[10-s].
    {
        float L[11];
#pragma unroll
        for (int s = 0; s <= 10; ++s) {
            float ps = __nv_powf(p, (float)s);
            float qf = __nv_powf(q, (float)(10 - s));
            L[s] = __fmul_rn(ps, qf);
        }
        float2* Tt = Tsh + tid;
#pragma unroll
        for (int s = 0; s <= 10; ++s) {
            Tt[s * BLK] = make_float2(L[s], L[10 - s]);
        }
    }
    if (!valid) return;   // private smem columns: no __syncthreads needed

    const float2* Tt = Tsh + tid;
    float prior = belief[i];
    float mst   = mistrust[i];

    const int4* nrow = (const int4*)(nbr + (long long)i * 64);

    // Depth-8 pipeline: groups g (A, resident), g+1 (B, arriving/resident),
    // g+2 (C, issued this iteration). n2 holds the nbr row for group g+2.
    int4 n2 = __ldcs(nrow + 2);
    int4 r01 = __ldcs(nrow + 0);
    int4 r11 = __ldcs(nrow + 1);
    uint2 A0 = __ldg(&g_records[r01.x]);
    uint2 A1 = __ldg(&g_records[r01.y]);
    uint2 A2 = __ldg(&g_records[r01.z]);
    uint2 A3 = __ldg(&g_records[r01.w]);
    uint2 B0 = __ldg(&g_records[r11.x]);
    uint2 B1 = __ldg(&g_records[r11.y]);
    uint2 B2 = __ldg(&g_records[r11.z]);
    uint2 B3 = __ldg(&g_records[r11.w]);

#pragma unroll
    for (int g = 0; g < 16; ++g) {
        uint2 C0, C1, C2, C3;
        int4  nn = n2;
        if (g <= 13) {                       // gather group g+2
            C0 = __ldg(&g_records[n2.x]);
            C1 = __ldg(&g_records[n2.y]);
            C2 = __ldg(&g_records[n2.z]);
            C3 = __ldg(&g_records[n2.w]);
        }
        if (g <= 12) nn = __ldcs(nrow + g + 3);   // nbr row for group g+3

        prior = fold_step(prior, A0, Tt, mst);
        prior = fold_step(prior, A1, Tt, mst);
        prior = fold_step(prior, A2, Tt, mst);
        prior = fold_step(prior, A3, Tt, mst);

        if (g <= 13) {
            A0 = B0; A1 = B1; A2 = B2; A3 = B3;
            B0 = C0; B1 = C1; B2 = C2; B3 = C3;
        } else {
            A0 = B0; A1 = B1; A2 = B2; A3 = B3;
        }
        n2 = nn;
    }

    out[i] = prior;
}

// Generic fallback for unexpected shapes: same (frozen) tree, direct gathers.
__global__ void fold_generic_kernel(const float* __restrict__ belief,
                                    const float* __restrict__ prob,
                                    const float* __restrict__ mistrust,
                                    const float* __restrict__ payoff,
                                    const int*   __restrict__ nbr,
                                    float*       __restrict__ out,
                                    int n, int K) {
    int i = blockIdx.x * blockDim.x + threadIdx.x;
    if (i >= n) return;
    float p = prob[i];
    float q = __fsub_rn(1.0f, p);
    float mst = mistrust[i];
    float prior = belief[i];
    for (int k = 0; k < K; ++k) {
        int j = nbr[(long long)i * K + k];
        float t = payoff[2 * j + 1];
        if (t > 0.0f) {
            float s = payoff[2 * j];
            float f = __fsub_rn(t, s);
            float b = belief[j];
            float lik = __fmul_rn(__nv_powf(p, s), __nv_powf(q, f));
            float alt = __fmul_rn(__nv_powf(q, s), __nv_powf(p, f));
            float delta = fabsf(__fsub_rn(prior, b));
            float pl    = __fmul_rn(prior, lik);
            float marg  = __fmaf_rn(__fsub_rn(1.0f, prior), alt, pl);
            float omm   = __fsub_rn(1.0f, marg);
            float bel   = __fdiv_rn(pl, marg);
            float mis   = __fdiv_rn(__fmul_rn(prior, __fsub_rn(1.0f, lik)), omm);
            float u     = __fmul_rn(delta, mst);
            float cert  = fmaxf(__fmaf_rn(-u, omm, 1.0f), 0.0f);
            prior = __fmaf_rn(bel, cert,
                              __fmul_rn(mis, __fsub_rn(1.0f, cert)));
        }
    }
    out[i] = prior;
}

extern "C" void kernel_launch(void* const* d_in, const int* in_sizes, int n_in,
                              void* d_out, int out_size) {
    const float* belief   = (const float*)d_in[0];
    const float* prob     = (const float*)d_in[1];
    const float* mistrust = (const float*)d_in[2];
    const float* payoff   = (const float*)d_in[3];
    const int*   nbr      = (const int*)d_in[4];
    float*       out      = (float*)d_out;

    int n = in_sizes[0];
    int K = (n > 0) ? (in_sizes[4] / n) : 0;

    int grid = (n + BLK - 1) / BLK;

    if (K == 64 && n <= MAXN) {
        pack_kernel<<<grid, BLK>>>(belief, (const float2*)payoff, n);
        fold_kernel<<<grid, BLK>>>(belief, prob, mistrust, nbr, out, n);
    } else {
        fold_generic_kernel<<<grid, BLK>>>(belief, prob, mistrust, payoff, nbr,
                                           out, n, K);
    }
}

// round 14
// speedup vs baseline: 1.1205x; 1.1205x over previous
#include <cuda_runtime.h>
#include <cuda.h>
#include <cuda_bf16.h>
#include <cstdint>
#include <dlfcn.h>

// -----------------------------------------------------------------------------
// OConnorWeatherall belief update, N=500000, K=64, TRIALS=10.
//
// PASSING arithmetic (R9, bit-exact vs GPU-jax/XLA:GPU — FROZEN):
//   pl   = rn(prior*lik)                      // two uses -> NOT fused (NVPTX)
//   marg = fma(1-prior, alt, pl)              // N1-side fusion
//   cert = max(fma(-(delta*mst), 1-marg, 1), 0)
//   post = fma(bel, cert, rn(mis*(1-cert)))
//   div.rn (__fdiv_rn); pow = libdevice __nv_powf.
//
// R14: nbr stream moved to TMA. The per-lane 256B-strided nbr rows cost
// 512 L1TEX wavefronts/warp as LDG; a 2D TMA (box 32B x 256 rows) lands the
// same data packed in smem (64 LDS wf/warp), double-buffered via mbarrier.
// Tensor map encoded host-side through dlopen'd cuTensorMapEncodeTiled;
// any failure falls back to the R10 kernel (best known 143.9us).
// -----------------------------------------------------------------------------

extern "C" __device__ float __nv_powf(float, float);   // libdevice (XLA:GPU pow)

#define MAXN 500000
#define BLK  256

__device__ __align__(8) static uint2 g_records[MAXN];

__global__ void pack_kernel(const float* __restrict__ belief,
                            const float2* __restrict__ payoff,
                            int n) {
    int i = blockIdx.x * blockDim.x + threadIdx.x;
    if (i >= n) return;
    float2 st = payoff[i];
    unsigned meta = 0u;
    if (st.y > 0.0f) {
        meta = 0x100u | (unsigned)__float2int_rn(st.x);
    }
    g_records[i] = make_uint2(__float_as_uint(belief[i]), meta);
}

__device__ __forceinline__ uint32_t smem_u32(const void* p) {
    uint32_t a;
    asm("{ .reg .u64 t; cvta.to.shared.u64 t, %1; cvt.u32.u64 %0, t; }"
        : "=r"(a) : "l"(p));
    return a;
}

__device__ __forceinline__ void mbar_wait(uint32_t mbar, uint32_t phase) {
    asm volatile(
        "{\n\t"
        ".reg .pred P1;\n\t"
        "LAB_%=:\n\t"
        "mbarrier.try_wait.parity.acquire.cta.shared::cta.b64 P1, [%0], %1, 0x989680;\n\t"
        "@P1 bra.uni DONE_%=;\n\t"
        "bra.uni LAB_%=;\n\t"
        "DONE_%=:\n\t"
        "}"
        :: "r"(mbar), "r"(phase) : "memory");
}

__device__ __forceinline__ void mbar_expect_tma(uint32_t mbar, uint32_t dst,
                                                const CUtensorMap* tmap,
                                                int x, int y) {
    asm volatile("mbarrier.arrive.expect_tx.shared.b64 _, [%0], %1;"
                 :: "r"(mbar), "r"(8192u) : "memory");
    asm volatile(
        "cp.async.bulk.tensor.2d.shared::cta.global.tile.mbarrier::complete_tx::bytes "
        "[%0], [%1, {%2, %3}], [%4];"
        :: "r"(dst), "l"(tmap), "r"(x), "r"(y), "r"(mbar) : "memory");
}

// One fold step: NVPTX hasOneUse-contracted tree (bit-exact, FROZEN).
// T = thread's private float2 smem column, stride BLK: T[s] = (lik_s, alt_s).
__device__ __forceinline__ float fold_step(float prior, uint2 rec,
                                           const float2* __restrict__ T,
                                           float mst) {
    unsigned meta = rec.y;
    if (meta & 0x100u) {
        float b   = __uint_as_float(rec.x);
        int   s   = (int)(meta & 0xFFu);
        float2 la = T[s * BLK];
        float lik = la.x;
        float alt = la.y;
        float delta = fabsf(__fsub_rn(prior, b));
        float pl    = __fmul_rn(prior, lik);
        float marg  = __fmaf_rn(__fsub_rn(1.0f, prior), alt, pl);
        float omm   = __fsub_rn(1.0f, marg);
        float bel   = __fdiv_rn(pl, marg);
        float mis   = __fdiv_rn(__fmul_rn(prior, __fsub_rn(1.0f, lik)), omm);
        float u     = __fmul_rn(delta, mst);
        float cert  = fmaxf(__fmaf_rn(-u, omm, 1.0f), 0.0f);
        prior = __fmaf_rn(bel, cert,
                          __fmul_rn(mis, __fsub_rn(1.0f, cert)));
    }
    return prior;
}

__device__ __forceinline__ void build_table(float p, float2* Tt) {
    float q = __fsub_rn(1.0f, p);
    float L[11];
#pragma unroll
    for (int s = 0; s <= 10; ++s) {
        float ps = __nv_powf(p, (float)s);
        float qf = __nv_powf(q, (float)(10 - s));
        L[s] = __fmul_rn(ps, qf);
    }
#pragma unroll
    for (int s = 0; s <= 10; ++s) {
        Tt[s * BLK] = make_float2(L[s], L[10 - s]);
    }
}

// ---- TMA-fed fold kernel ----------------------------------------------------

__global__ __launch_bounds__(BLK, 5)
void fold_tma_kernel(const __grid_constant__ CUtensorMap tmap,
                     const float* __restrict__ belief,
                     const float* __restrict__ prob,
                     const float* __restrict__ mistrust,
                     float* __restrict__ out, int n) {
    __shared__ __align__(1024) unsigned char NbrBuf[2][8192];
    __shared__ float2 Tsh[11 * BLK];
    __shared__ __align__(8) unsigned long long Mbar[2];

    int tid  = threadIdx.x;
    int base = blockIdx.x * BLK;
    int iraw = base + tid;
    bool valid = (iraw < n);
    int i = valid ? iraw : (n - 1);        // clamp: every thread stays resident

    uint32_t mb[2]  = { smem_u32(&Mbar[0]), smem_u32(&Mbar[1]) };
    uint32_t buf[2] = { smem_u32(&NbrBuf[0][0]), smem_u32(&NbrBuf[1][0]) };

    if (tid == 0) {
        asm volatile("mbarrier.init.shared.b64 [%0], 1;" :: "r"(mb[0]) : "memory");
        asm volatile("mbarrier.init.shared.b64 [%0], 1;" :: "r"(mb[1]) : "memory");
    }
    __syncthreads();
    if (tid == 0) {
        mbar_expect_tma(mb[0], buf[0], &tmap, 0,  base);   // chunk 0 (k 0..7)
        mbar_expect_tma(mb[1], buf[1], &tmap, 32, base);   // chunk 1 (k 8..15)
    }

    // Table build overlaps the first TMA.
    float2* Tt = Tsh + tid;
    build_table(prob[i], Tt);
    float prior = belief[i];
    float mst   = mistrust[i];

    // Chunk c holds bytes [32c,32c+32) of each row = groups 2c, 2c+1.
    mbar_wait(mb[0], 0);
    const int4* R0 = (const int4*)NbrBuf[0];
    const int4* R1 = (const int4*)NbrBuf[1];

    int4 j = R0[tid * 2 + 0];
    uint2 A0 = __ldg(&g_records[j.x]);
    uint2 A1 = __ldg(&g_records[j.y]);
    uint2 A2 = __ldg(&g_records[j.z]);
    uint2 A3 = __ldg(&g_records[j.w]);
    j = R0[tid * 2 + 1];
    uint2 B0 = __ldg(&g_records[j.x]);
    uint2 B1 = __ldg(&g_records[j.y]);
    uint2 B2 = __ldg(&g_records[j.z]);
    uint2 B3 = __ldg(&g_records[j.w]);

#pragma unroll
    for (int c = 0; c < 8; ++c) {
        __syncthreads();   // all threads done reading chunk c (read in iter c-1)
        if (c + 2 <= 7 && tid == 0) {
            mbar_expect_tma(mb[c & 1], buf[c & 1], &tmap, (c + 2) * 32, base);
        }
        uint2 C0, C1, C2, C3, D0, D1, D2, D3;
        const int4* RN = ((c + 1) & 1) ? R1 : R0;
        if (c < 7) {
            mbar_wait(mb[(c + 1) & 1], ((c + 1) >> 1) & 1);
            int4 jc = RN[tid * 2 + 0];              // group 2c+2
            C0 = __ldg(&g_records[jc.x]);
            C1 = __ldg(&g_records[jc.y]);
            C2 = __ldg(&g_records[jc.z]);
            C3 = __ldg(&g_records[jc.w]);
        }
        prior = fold_step(prior, A0, Tt, mst);
        prior = fold_step(prior, A1, Tt, mst);
        prior = fold_step(prior, A2, Tt, mst);
        prior = fold_step(prior, A3, Tt, mst);
        if (c < 7) {
            int4 jd = RN[tid * 2 + 1];              // group 2c+3
            D0 = __ldg(&g_records[jd.x]);
            D1 = __ldg(&g_records[jd.y]);
            D2 = __ldg(&g_records[jd.z]);
            D3 = __ldg(&g_records[jd.w]);
        }
        prior = fold_step(prior, B0, Tt, mst);
        prior = fold_step(prior, B1, Tt, mst);
        prior = fold_step(prior, B2, Tt, mst);
        prior = fold_step(prior, B3, Tt, mst);
        if (c < 7) {
            A0 = C0; A1 = C1; A2 = C2; A3 = C3;
            B0 = D0; B1 = D1; B2 = D2; B3 = D3;
        }
    }

    if (valid) out[i] = prior;
}

// ---- R10 fallback fold kernel (best known non-TMA: 143.9us) -----------------

__global__ __launch_bounds__(BLK)
void fold_kernel(const float* __restrict__ belief,
                 const float* __restrict__ prob,
                 const float* __restrict__ mistrust,
                 const int*   __restrict__ nbr,
                 float*       __restrict__ out,
                 int n) {
    __shared__ float2 Tsh[11 * BLK];
    int tid = threadIdx.x;
    int i = blockIdx.x * BLK + tid;
    bool valid = (i < n);

    float p = valid ? prob[i] : 0.7f;
    build_table(p, Tsh + tid);
    if (!valid) return;

    const float2* Tt = Tsh + tid;
    float prior = belief[i];
    float mst   = mistrust[i];

    const int4* nrow = (const int4*)(nbr + (long long)i * 64);

    int4 n2 = __ldcs(nrow + 2);
    int4 r01 = __ldcs(nrow + 0);
    int4 r11 = __ldcs(nrow + 1);
    uint2 A0 = __ldg(&g_records[r01.x]);
    uint2 A1 = __ldg(&g_records[r01.y]);
    uint2 A2 = __ldg(&g_records[r01.z]);
    uint2 A3 = __ldg(&g_records[r01.w]);
    uint2 B0 = __ldg(&g_records[r11.x]);
    uint2 B1 = __ldg(&g_records[r11.y]);
    uint2 B2 = __ldg(&g_records[r11.z]);
    uint2 B3 = __ldg(&g_records[r11.w]);

#pragma unroll
    for (int g = 0; g < 16; ++g) {
        uint2 C0, C1, C2, C3;
        int4  nn = n2;
        if (g <= 13) {
            C0 = __ldg(&g_records[n2.x]);
            C1 = __ldg(&g_records[n2.y]);
            C2 = __ldg(&g_records[n2.z]);
            C3 = __ldg(&g_records[n2.w]);
        }
        if (g <= 12) nn = __ldcs(nrow + g + 3);

        prior = fold_step(prior, A0, Tt, mst);
        prior = fold_step(prior, A1, Tt, mst);
        prior = fold_step(prior, A2, Tt, mst);
        prior = fold_step(prior, A3, Tt, mst);

        if (g <= 13) {
            A0 = B0; A1 = B1; A2 = B2; A3 = B3;
            B0 = C0; B1 = C1; B2 = C2; B3 = C3;
        } else {
            A0 = B0; A1 = B1; A2 = B2; A3 = B3;
        }
        n2 = nn;
    }

    out[i] = prior;
}

// ---- generic fallback (unexpected shapes) -----------------------------------

__global__ void fold_generic_kernel(const float* __restrict__ belief,
                                    const float* __restrict__ prob,
                                    const float* __restrict__ mistrust,
                                    const float* __restrict__ payoff,
                                    const int*   __restrict__ nbr,
                                    float*       __restrict__ out,
                                    int n, int K) {
    int i = blockIdx.x * blockDim.x + threadIdx.x;
    if (i >= n) return;
    float p = prob[i];
    float q = __fsub_rn(1.0f, p);
    float mst = mistrust[i];
    float prior = belief[i];
    for (int k = 0; k < K; ++k) {
        int j = nbr[(long long)i * K + k];
        float t = payoff[2 * j + 1];
        if (t > 0.0f) {
            float s = payoff[2 * j];
            float f = __fsub_rn(t, s);
            float b = belief[j];
            float lik = __fmul_rn(__nv_powf(p, s), __nv_powf(q, f));
            float alt = __fmul_rn(__nv_powf(q, s), __nv_powf(p, f));
            float delta = fabsf(__fsub_rn(prior, b));
            float pl    = __fmul_rn(prior, lik);
            float marg  = __fmaf_rn(__fsub_rn(1.0f, prior), alt, pl);
            float omm   = __fsub_rn(1.0f, marg);
            float bel   = __fdiv_rn(pl, marg);
            float mis   = __fdiv_rn(__fmul_rn(prior, __fsub_rn(1.0f, lik)), omm);
            float u     = __fmul_rn(delta, mst);
            float cert  = fmaxf(__fmaf_rn(-u, omm, 1.0f), 0.0f);
            prior = __fmaf_rn(bel, cert,
                              __fmul_rn(mis, __fsub_rn(1.0f, cert)));
        }
    }
    out[i] = prior;
}

// ---- host -------------------------------------------------------------------

typedef CUresult (*EncodeFn)(CUtensorMap*, CUtensorMapDataType, cuuint32_t,
                             void*, const cuuint64_t*, const cuuint64_t*,
                             const cuuint32_t*, const cuuint32_t*,
                             CUtensorMapInterleave, CUtensorMapSwizzle,
                             CUtensorMapL2promotion, CUtensorMapFloatOOBfill);

extern "C" void kernel_launch(void* const* d_in, const int* in_sizes, int n_in,
                              void* d_out, int out_size) {
    const float* belief   = (const float*)d_in[0];
    const float* prob     = (const float*)d_in[1];
    const float* mistrust = (const float*)d_in[2];
    const float* payoff   = (const float*)d_in[3];
    const int*   nbr      = (const int*)d_in[4];
    float*       out      = (float*)d_out;

    int n = in_sizes[0];
    int K = (n > 0) ? (in_sizes[4] / n) : 0;
    int grid = (n + BLK - 1) / BLK;

    if (K == 64 && n <= MAXN && n > 0) {
        // Try to build the nbr tensor map: rows of 256B, box 32B x 256 rows.
        bool tma_ok = false;
        CUtensorMap tmap;
        if (((uintptr_t)nbr & 0xF) == 0) {
            void* h = dlopen("libcuda.so.1", RTLD_NOW | RTLD_GLOBAL);
            if (!h) h = dlopen("libcuda.so", RTLD_NOW | RTLD_GLOBAL);
            if (h) {
                EncodeFn fn = (EncodeFn)dlsym(h, "cuTensorMapEncodeTiled");
                if (fn) {
                    cuuint64_t dims[2]    = { 256ull, (cuuint64_t)n };
                    cuuint64_t strides[1] = { 256ull };
                    cuuint32_t box[2]     = { 32u, 256u };
                    cuuint32_t estr[2]    = { 1u, 1u };
                    CUresult r = fn(&tmap, CU_TENSOR_MAP_DATA_TYPE_UINT8, 2,
                                    (void*)nbr, dims, strides, box, estr,
                                    CU_TENSOR_MAP_INTERLEAVE_NONE,
                                    CU_TENSOR_MAP_SWIZZLE_NONE,
                                    CU_TENSOR_MAP_L2_PROMOTION_L2_128B,
                                    CU_TENSOR_MAP_FLOAT_OOB_FILL_NONE);
                    tma_ok = (r == CUDA_SUCCESS);
                }
            }
        }
        pack_kernel<<<grid, BLK>>>(belief, (const float2*)payoff, n);
        if (tma_ok) {
            fold_tma_kernel<<<grid, BLK>>>(tmap, belief, prob, mistrust, out, n);
        } else {
            fold_kernel<<<grid, BLK>>>(belief, prob, mistrust, nbr, out, n);
        }
    } else {
        fold_generic_kernel<<<grid, BLK>>>(belief, prob, mistrust, payoff, nbr,
                                           out, n, K);
    }
}